// round 1
// baseline (speedup 1.0000x reference)
#include <cuda_runtime.h>
#include <mma.h>
#include <math.h>

using namespace nvcuda;

#define T_TOKENS 4096
#define DMODEL   1024
#define DFFN     4096
#define NEXP     8
#define TOPK     2
#define NSLOTS   (T_TOKENS * TOPK)

// ---- scratch (__device__ globals; allocation-free rule) ----
__device__ float g_h[(size_t)NSLOTS * DFFN];   // 128 MiB intermediate activations
__device__ int   g_tok[NSLOTS];
__device__ float g_gate[NSLOTS];
__device__ int   g_counts[NEXP];
__device__ int   g_cursor[NEXP];
__device__ int   g_off[NEXP + 1];
__device__ int   g_topi[T_TOKENS * TOPK];
__device__ float g_topg[T_TOKENS * TOPK];

// ---------------------------------------------------------------------------
__global__ void reset_kernel(float4* out, int n4) {
    int idx = blockIdx.x * blockDim.x + threadIdx.x;
    float4 z = make_float4(0.f, 0.f, 0.f, 0.f);
    for (int i = idx; i < n4; i += gridDim.x * blockDim.x) out[i] = z;
    if (idx < NEXP) g_counts[idx] = 0;
}

// One warp per token: noisy top-2 router.
__global__ void router_kernel(const float* __restrict__ x, const float* __restrict__ noise,
                              const float* __restrict__ Wg, const float* __restrict__ bg,
                              const float* __restrict__ Wn, const float* __restrict__ bn) {
    int gw = (blockIdx.x * blockDim.x + threadIdx.x) >> 5;
    int lane = threadIdx.x & 31;
    if (gw >= T_TOKENS) return;
    const float* xr = x + (size_t)gw * DMODEL;
    float lg[NEXP], ln[NEXP];
#pragma unroll
    for (int e = 0; e < NEXP; e++) { lg[e] = 0.f; ln[e] = 0.f; }
    for (int d = lane; d < DMODEL; d += 32) {
        float xv = xr[d];
#pragma unroll
        for (int e = 0; e < NEXP; e++) {
            lg[e] += xv * Wg[d * NEXP + e];
            ln[e] += xv * Wn[d * NEXP + e];
        }
    }
#pragma unroll
    for (int o = 16; o > 0; o >>= 1) {
#pragma unroll
        for (int e = 0; e < NEXP; e++) {
            lg[e] += __shfl_xor_sync(0xffffffffu, lg[e], o);
            ln[e] += __shfl_xor_sync(0xffffffffu, ln[e], o);
        }
    }
    if (lane == 0) {
        float nv[NEXP];
#pragma unroll
        for (int e = 0; e < NEXP; e++) {
            float nl = ln[e] + bn[e];
            float sp = (nl > 20.f) ? nl : log1pf(expf(nl));   // softplus
            nv[e] = lg[e] + bg[e] + noise[gw * NEXP + e] * sp;
        }
        int i0 = 0;
#pragma unroll
        for (int e = 1; e < NEXP; e++) if (nv[e] > nv[i0]) i0 = e;
        int i1 = (i0 == 0) ? 1 : 0;
#pragma unroll
        for (int e = 0; e < NEXP; e++) if (e != i0 && nv[e] > nv[i1]) i1 = e;
        // softmax over the two kept logits (others are -inf in reference)
        float e1 = expf(nv[i1] - nv[i0]);
        float s = 1.f + e1;
        g_topi[gw * 2]     = i0;  g_topg[gw * 2]     = 1.f / s;
        g_topi[gw * 2 + 1] = i1;  g_topg[gw * 2 + 1] = e1 / s;
        atomicAdd(&g_counts[i0], 1);
        atomicAdd(&g_counts[i1], 1);
    }
}

__global__ void offsets_kernel() {
    if (threadIdx.x == 0) {
        int acc = 0;
        for (int e = 0; e < NEXP; e++) {
            g_off[e] = acc; g_cursor[e] = acc; acc += g_counts[e];
        }
        g_off[NEXP] = acc;   // == NSLOTS
    }
}

__global__ void scatter_kernel() {
    int t = blockIdx.x * blockDim.x + threadIdx.x;
    if (t >= T_TOKENS) return;
#pragma unroll
    for (int k = 0; k < TOPK; k++) {
        int e = g_topi[t * 2 + k];
        int pos = atomicAdd(&g_cursor[e], 1);
        g_tok[pos]  = t;
        g_gate[pos] = g_topg[t * 2 + k];
    }
}

// ---------------------------------------------------------------------------
// Grouped GEMM, tf32 wmma. PHASE 0: h = relu(gather(x) @ W1 + b1)
//                           PHASE 1: out += gate * (h @ W2 + b2)
#define BM 128
#define BN 128
#define BK 32
#define LDA 36
#define LDB 132
#define LDSG 136

template <int PHASE>
__global__ __launch_bounds__(256)
void moe_gemm_kernel(const float* __restrict__ x,
                     const float* __restrict__ W1, const float* __restrict__ b1,
                     const float* __restrict__ W2, const float* __restrict__ b2,
                     float* __restrict__ out) {
    const int K  = PHASE ? DFFN : DMODEL;
    const int NN = PHASE ? DMODEL : DFFN;
    int e  = blockIdx.x >> 5;       // expert
    int mt = blockIdx.x & 31;       // M tile within expert (capacity 4096 rows)
    int off0  = g_off[e];
    int count = g_off[e + 1] - off0;
    if (mt * BM >= count) return;   // inactive tile
    int n0 = blockIdx.y * BN;

    __shared__ float smem[BM * LDA + BK * LDB];   // 8832 floats; stage (64*136=8704) fits
    float* As = smem;
    float* Bs = smem + BM * LDA;

    int tid  = threadIdx.x;
    int warp = tid >> 5;
    int wm = warp & 3;              // 4 warps along M (32 rows each)
    int wn = warp >> 2;             // 2 warps along N (64 cols each)

    wmma::fragment<wmma::accumulator, 16, 16, 8, float> acc[2][4];
#pragma unroll
    for (int i = 0; i < 2; i++)
#pragma unroll
        for (int j = 0; j < 4; j++) wmma::fill_fragment(acc[i][j], 0.f);

    const float* Bsrc = PHASE ? (W2 + (size_t)e * DFFN * DMODEL)
                              : (W1 + (size_t)e * DMODEL * DFFN);

    // Per-thread global A-row base pointers (4 float4 loads / thread / k-step)
    const float* Arow[4];
#pragma unroll
    for (int i = 0; i < 4; i++) {
        int idx = tid + i * 256;
        int r = idx >> 3;                         // 0..127
        int lr = mt * BM + r;
        int lrc = (lr < count) ? lr : (count - 1);   // clamp ragged edge
        int slot = off0 + lrc;
        if (PHASE) Arow[i] = g_h + (size_t)slot * DFFN;
        else       Arow[i] = x + (size_t)g_tok[slot] * DMODEL;
    }

    for (int k0 = 0; k0 < K; k0 += BK) {
        __syncthreads();
#pragma unroll
        for (int i = 0; i < 4; i++) {             // A tile: 128 x 32
            int idx = tid + i * 256;
            int r = idx >> 3, c4 = idx & 7;
            float4 v = *(const float4*)(Arow[i] + k0 + c4 * 4);
            *(float4*)(As + r * LDA + c4 * 4) = v;
        }
#pragma unroll
        for (int i = 0; i < 4; i++) {             // B tile: 32 x 128
            int idx = tid + i * 256;
            int kr = idx >> 5, c4 = idx & 31;
            float4 v = *(const float4*)(Bsrc + (size_t)(k0 + kr) * NN + n0 + c4 * 4);
            *(float4*)(Bs + kr * LDB + c4 * 4) = v;
        }
        __syncthreads();
#pragma unroll
        for (int kk = 0; kk < BK; kk += 8) {
            wmma::fragment<wmma::matrix_a, 16, 16, 8, wmma::precision::tf32, wmma::row_major> af[2];
            wmma::fragment<wmma::matrix_b, 16, 16, 8, wmma::precision::tf32, wmma::row_major> bf[4];
#pragma unroll
            for (int i = 0; i < 2; i++) {
                wmma::load_matrix_sync(af[i], As + (wm * 32 + i * 16) * LDA + kk, LDA);
#pragma unroll
                for (int t = 0; t < af[i].num_elements; t++)
                    af[i].x[t] = wmma::__float_to_tf32(af[i].x[t]);
            }
#pragma unroll
            for (int j = 0; j < 4; j++) {
                wmma::load_matrix_sync(bf[j], Bs + kk * LDB + wn * 64 + j * 16, LDB);
#pragma unroll
                for (int t = 0; t < bf[j].num_elements; t++)
                    bf[j].x[t] = wmma::__float_to_tf32(bf[j].x[t]);
            }
#pragma unroll
            for (int i = 0; i < 2; i++)
#pragma unroll
                for (int j = 0; j < 4; j++)
                    wmma::mma_sync(acc[i][j], af[i], bf[j], acc[i][j]);
        }
    }

    // Epilogue: stage through smem in two 64-row halves (predicated ragged rows)
    float* stage = smem;
#pragma unroll
    for (int h = 0; h < 2; h++) {
        __syncthreads();
        if ((wm >> 1) == h) {
            int lm = wm & 1;
#pragma unroll
            for (int i = 0; i < 2; i++)
#pragma unroll
                for (int j = 0; j < 4; j++)
                    wmma::store_matrix_sync(stage + (lm * 32 + i * 16) * LDSG + wn * 64 + j * 16,
                                            acc[i][j], LDSG, wmma::mem_row_major);
        }
        __syncthreads();
        for (int idx = tid; idx < 64 * BN; idx += 256) {
            int r = idx >> 7;
            int c = idx & 127;
            int lr = mt * BM + h * 64 + r;
            if (lr < count) {
                float v = stage[r * LDSG + c];
                int slot = off0 + lr;
                if (PHASE == 0) {
                    v += b1[e * DFFN + n0 + c];
                    v = fmaxf(v, 0.f);
                    g_h[(size_t)slot * DFFN + n0 + c] = v;
                } else {
                    v += b2[e * DMODEL + n0 + c];
                    v *= g_gate[slot];
                    atomicAdd(&out[(size_t)g_tok[slot] * DMODEL + n0 + c], v);
                }
            }
        }
    }
}

// ---------------------------------------------------------------------------
extern "C" void kernel_launch(void* const* d_in, const int* in_sizes, int n_in,
                              void* d_out, int out_size) {
    const float* x     = (const float*)d_in[0];
    const float* noise = (const float*)d_in[1];
    const float* Wg    = (const float*)d_in[2];
    const float* bg    = (const float*)d_in[3];
    const float* Wn    = (const float*)d_in[4];
    const float* bn    = (const float*)d_in[5];
    const float* W1    = (const float*)d_in[6];
    const float* b1    = (const float*)d_in[7];
    const float* W2    = (const float*)d_in[8];
    const float* b2    = (const float*)d_in[9];
    float* out = (float*)d_out;

    reset_kernel<<<1024, 256>>>((float4*)out, out_size / 4);
    router_kernel<<<(T_TOKENS * 32) / 256, 256>>>(x, noise, Wg, bg, Wn, bn);
    offsets_kernel<<<1, 32>>>();
    scatter_kernel<<<T_TOKENS / 256, 256>>>();

    dim3 g1(NEXP * 32, DFFN / BN);    // fc1: N tiles = 32
    moe_gemm_kernel<0><<<g1, 256>>>(x, W1, b1, W2, b2, out);
    dim3 g2(NEXP * 32, DMODEL / BN);  // fc2: N tiles = 8
    moe_gemm_kernel<1><<<g2, 256>>>(x, W1, b1, W2, b2, out);
}

// round 3
// speedup vs baseline: 1.1413x; 1.1413x over previous
#include <cuda_runtime.h>
#include <mma.h>
#include <math.h>
#include <cstdint>
#include <stdint.h>

using namespace nvcuda;

#define T_TOKENS 4096
#define DMODEL   1024
#define DFFN     4096
#define NEXP     8
#define TOPK     2
#define NSLOTS   (T_TOKENS * TOPK)

// ---- scratch (__device__ globals; allocation-free rule) ----
__device__ float g_h[(size_t)NSLOTS * DFFN];   // 128 MiB intermediate activations
__device__ int   g_tok[NSLOTS];
__device__ float g_gate[NSLOTS];
__device__ int   g_counts[NEXP];
__device__ int   g_cursor[NEXP];
__device__ int   g_off[NEXP + 1];
__device__ int   g_topi[T_TOKENS * TOPK];
__device__ float g_topg[T_TOKENS * TOPK];

// ---------------------------------------------------------------------------
__global__ void reset_kernel(float4* out, int n4) {
    int idx = blockIdx.x * blockDim.x + threadIdx.x;
    float4 z = make_float4(0.f, 0.f, 0.f, 0.f);
    for (int i = idx; i < n4; i += gridDim.x * blockDim.x) out[i] = z;
    if (idx < NEXP) g_counts[idx] = 0;
}

// One warp per token: noisy top-2 router.
__global__ void router_kernel(const float* __restrict__ x, const float* __restrict__ noise,
                              const float* __restrict__ Wg, const float* __restrict__ bg,
                              const float* __restrict__ Wn, const float* __restrict__ bn) {
    int gw = (blockIdx.x * blockDim.x + threadIdx.x) >> 5;
    int lane = threadIdx.x & 31;
    if (gw >= T_TOKENS) return;
    const float* xr = x + (size_t)gw * DMODEL;
    float lg[NEXP], ln[NEXP];
#pragma unroll
    for (int e = 0; e < NEXP; e++) { lg[e] = 0.f; ln[e] = 0.f; }
    for (int d = lane; d < DMODEL; d += 32) {
        float xv = xr[d];
#pragma unroll
        for (int e = 0; e < NEXP; e++) {
            lg[e] += xv * Wg[d * NEXP + e];
            ln[e] += xv * Wn[d * NEXP + e];
        }
    }
#pragma unroll
    for (int o = 16; o > 0; o >>= 1) {
#pragma unroll
        for (int e = 0; e < NEXP; e++) {
            lg[e] += __shfl_xor_sync(0xffffffffu, lg[e], o);
            ln[e] += __shfl_xor_sync(0xffffffffu, ln[e], o);
        }
    }
    if (lane == 0) {
        float nv[NEXP];
#pragma unroll
        for (int e = 0; e < NEXP; e++) {
            float nl = ln[e] + bn[e];
            float sp = (nl > 20.f) ? nl : log1pf(expf(nl));   // softplus
            nv[e] = lg[e] + bg[e] + noise[gw * NEXP + e] * sp;
        }
        int i0 = 0;
#pragma unroll
        for (int e = 1; e < NEXP; e++) if (nv[e] > nv[i0]) i0 = e;
        int i1 = (i0 == 0) ? 1 : 0;
#pragma unroll
        for (int e = 0; e < NEXP; e++) if (e != i0 && nv[e] > nv[i1]) i1 = e;
        float e1 = expf(nv[i1] - nv[i0]);
        float s = 1.f + e1;
        g_topi[gw * 2]     = i0;  g_topg[gw * 2]     = 1.f / s;
        g_topi[gw * 2 + 1] = i1;  g_topg[gw * 2 + 1] = e1 / s;
        atomicAdd(&g_counts[i0], 1);
        atomicAdd(&g_counts[i1], 1);
    }
}

__global__ void offsets_kernel() {
    if (threadIdx.x == 0) {
        int acc = 0;
        for (int e = 0; e < NEXP; e++) {
            g_off[e] = acc; g_cursor[e] = acc; acc += g_counts[e];
        }
        g_off[NEXP] = acc;
    }
}

__global__ void scatter_kernel() {
    int t = blockIdx.x * blockDim.x + threadIdx.x;
    if (t >= T_TOKENS) return;
#pragma unroll
    for (int k = 0; k < TOPK; k++) {
        int e = g_topi[t * 2 + k];
        int pos = atomicAdd(&g_cursor[e], 1);
        g_tok[pos]  = t;
        g_gate[pos] = g_topg[t * 2 + k];
    }
}

// ---------------------------------------------------------------------------
// cp.async helpers
__device__ __forceinline__ void cp_async16(float* dst_smem, const float* src) {
    unsigned int d = (unsigned int)__cvta_generic_to_shared(dst_smem);
    asm volatile("cp.async.cg.shared.global [%0], [%1], 16;\n" :: "r"(d), "l"(src));
}
#define CP_COMMIT() asm volatile("cp.async.commit_group;\n" ::: "memory")

// ---------------------------------------------------------------------------
// Grouped GEMM, tf32 wmma, 2-stage cp.async pipeline.
//   PHASE 0: h = relu(gather(x) @ W1 + b1)
//   PHASE 1: out += gate * (h @ W2 + b2)
#define BM 128
#define BN 128
#define BK 32
#define LDA 36
#define LDB 132
#define LDSG 136
#define STAGE_FLOATS (BM * LDA + BK * LDB)   // 8832 floats = 34.5 KB per stage

template <int PHASE>
__global__ __launch_bounds__(256)
void moe_gemm_kernel(const float* __restrict__ x,
                     const float* __restrict__ W1, const float* __restrict__ b1,
                     const float* __restrict__ W2, const float* __restrict__ b2,
                     float* __restrict__ out) {
    const int K  = PHASE ? DFFN : DMODEL;
    const int NN = PHASE ? DMODEL : DFFN;
    int e  = blockIdx.x >> 5;       // expert
    int mt = blockIdx.x & 31;       // M tile within expert
    int off0  = g_off[e];
    int count = g_off[e + 1] - off0;
    if (mt * BM >= count) return;
    int n0 = blockIdx.y * BN;

    extern __shared__ float smem[];          // 2 * STAGE_FLOATS

    int tid  = threadIdx.x;
    int warp = tid >> 5;
    int wm = warp & 3;              // 4 warps along M (32 rows each)
    int wn = warp >> 2;             // 2 warps along N (64 cols each)

    wmma::fragment<wmma::accumulator, 16, 16, 8, float> acc[2][4];
#pragma unroll
    for (int i = 0; i < 2; i++)
#pragma unroll
        for (int j = 0; j < 4; j++) wmma::fill_fragment(acc[i][j], 0.f);

    const float* Bsrc = PHASE ? (W2 + (size_t)e * DFFN * DMODEL)
                              : (W1 + (size_t)e * DMODEL * DFFN);

    // Per-thread global A-row base pointers (4x 16B cp.async / thread / stage)
    const float* Arow[4];
#pragma unroll
    for (int i = 0; i < 4; i++) {
        int idx = tid + i * 256;
        int r = idx >> 3;                            // 0..127
        int lr = mt * BM + r;
        int lrc = (lr < count) ? lr : (count - 1);   // clamp ragged edge
        int slot = off0 + lrc;
        if (PHASE) Arow[i] = g_h + (size_t)slot * DFFN;
        else       Arow[i] = x + (size_t)g_tok[slot] * DMODEL;
    }

    const int nIter = K / BK;

    // ---- pipeline prefetch of a stage ----
    auto prefetch = [&](int s, int k0) {
        float* As = smem + s * STAGE_FLOATS;
        float* Bs = As + BM * LDA;
#pragma unroll
        for (int i = 0; i < 4; i++) {                // A tile: 128 x 32
            int idx = tid + i * 256;
            int r = idx >> 3, c4 = idx & 7;
            cp_async16(As + r * LDA + c4 * 4, Arow[i] + k0 + c4 * 4);
        }
#pragma unroll
        for (int i = 0; i < 4; i++) {                // B tile: 32 x 128
            int idx = tid + i * 256;
            int kr = idx >> 5, c4 = idx & 31;
            cp_async16(Bs + kr * LDB + c4 * 4,
                       Bsrc + (size_t)(k0 + kr) * NN + n0 + c4 * 4);
        }
    };

    prefetch(0, 0);
    CP_COMMIT();

    for (int it = 0; it < nIter; it++) {
        if (it + 1 < nIter) {
            prefetch((it + 1) & 1, (it + 1) * BK);
            CP_COMMIT();
            asm volatile("cp.async.wait_group 1;\n" ::: "memory");
        } else {
            asm volatile("cp.async.wait_group 0;\n" ::: "memory");
        }
        __syncthreads();

        float* As = smem + (it & 1) * STAGE_FLOATS;
        float* Bs = As + BM * LDA;
#pragma unroll
        for (int kk = 0; kk < BK; kk += 8) {
            wmma::fragment<wmma::matrix_a, 16, 16, 8, wmma::precision::tf32, wmma::row_major> af[2];
            wmma::fragment<wmma::matrix_b, 16, 16, 8, wmma::precision::tf32, wmma::row_major> bf[4];
#pragma unroll
            for (int i = 0; i < 2; i++) {
                wmma::load_matrix_sync(af[i], As + (wm * 32 + i * 16) * LDA + kk, LDA);
#pragma unroll
                for (int t = 0; t < af[i].num_elements; t++)
                    af[i].x[t] = wmma::__float_to_tf32(af[i].x[t]);
            }
#pragma unroll
            for (int j = 0; j < 4; j++) {
                wmma::load_matrix_sync(bf[j], Bs + kk * LDB + wn * 64 + j * 16, LDB);
#pragma unroll
                for (int t = 0; t < bf[j].num_elements; t++)
                    bf[j].x[t] = wmma::__float_to_tf32(bf[j].x[t]);
            }
#pragma unroll
            for (int i = 0; i < 2; i++)
#pragma unroll
                for (int j = 0; j < 4; j++)
                    wmma::mma_sync(acc[i][j], af[i], bf[j], acc[i][j]);
        }
        __syncthreads();   // protect the buffer the next prefetch overwrites
    }

    // Epilogue: stage through smem in two 64-row halves (predicated ragged rows)
    float* stage = smem;
#pragma unroll
    for (int h = 0; h < 2; h++) {
        __syncthreads();
        if ((wm >> 1) == h) {
            int lm = wm & 1;
#pragma unroll
            for (int i = 0; i < 2; i++)
#pragma unroll
                for (int j = 0; j < 4; j++)
                    wmma::store_matrix_sync(stage + (lm * 32 + i * 16) * LDSG + wn * 64 + j * 16,
                                            acc[i][j], LDSG, wmma::mem_row_major);
        }
        __syncthreads();
        for (int idx = tid; idx < 64 * BN; idx += 256) {
            int r = idx >> 7;
            int c = idx & 127;
            int lr = mt * BM + h * 64 + r;
            if (lr < count) {
                float v = stage[r * LDSG + c];
                int slot = off0 + lr;
                if (PHASE == 0) {
                    v += b1[e * DFFN + n0 + c];
                    v = fmaxf(v, 0.f);
                    g_h[(size_t)slot * DFFN + n0 + c] = v;
                } else {
                    v += b2[e * DMODEL + n0 + c];
                    v *= g_gate[slot];
                    atomicAdd(&out[(size_t)g_tok[slot] * DMODEL + n0 + c], v);
                }
            }
        }
    }
}

// ---------------------------------------------------------------------------
extern "C" void kernel_launch(void* const* d_in, const int* in_sizes, int n_in,
                              void* d_out, int out_size) {
    const float* x     = (const float*)d_in[0];
    const float* noise = (const float*)d_in[1];
    const float* Wg    = (const float*)d_in[2];
    const float* bg    = (const float*)d_in[3];
    const float* Wn    = (const float*)d_in[4];
    const float* bn    = (const float*)d_in[5];
    const float* W1    = (const float*)d_in[6];
    const float* b1    = (const float*)d_in[7];
    const float* W2    = (const float*)d_in[8];
    const float* b2    = (const float*)d_in[9];
    float* out = (float*)d_out;

    const int smem_bytes = 2 * STAGE_FLOATS * sizeof(float);   // 70656
    cudaFuncSetAttribute(moe_gemm_kernel<0>, cudaFuncAttributeMaxDynamicSharedMemorySize, smem_bytes);
    cudaFuncSetAttribute(moe_gemm_kernel<1>, cudaFuncAttributeMaxDynamicSharedMemorySize, smem_bytes);

    reset_kernel<<<1024, 256>>>((float4*)out, out_size / 4);
    router_kernel<<<(T_TOKENS * 32) / 256, 256>>>(x, noise, Wg, bg, Wn, bn);
    offsets_kernel<<<1, 32>>>();
    scatter_kernel<<<T_TOKENS / 256, 256>>>();

    dim3 g1(NEXP * 32, DFFN / BN);    // fc1
    moe_gemm_kernel<0><<<g1, 256, smem_bytes>>>(x, W1, b1, W2, b2, out);
    dim3 g2(NEXP * 32, DMODEL / BN);  // fc2
    moe_gemm_kernel<1><<<g2, 256, smem_bytes>>>(x, W1, b1, W2, b2, out);
}

// round 5
// speedup vs baseline: 2.8368x; 2.4857x over previous
#include <cuda_runtime.h>
#include <math.h>
#include <cstdint>
#include <stdint.h>

#define T_TOKENS 4096
#define DMODEL   1024
#define DFFN     4096
#define NEXP     8
#define TOPK     2
#define NSLOTS   (T_TOKENS * TOPK)
#define MT_MAX   64

// ---- scratch (__device__ globals; allocation-free rule) ----
__device__ float g_h[(size_t)NSLOTS * DFFN];   // 128 MiB intermediate activations
__device__ int   g_tok[NSLOTS];
__device__ float g_gate[NSLOTS];
__device__ int   g_counts[NEXP];
__device__ int   g_cursor[NEXP];
__device__ int   g_off[NEXP + 1];
__device__ int   g_topi[T_TOKENS * TOPK];
__device__ float g_topg[T_TOKENS * TOPK];

// ---------------------------------------------------------------------------
__device__ __forceinline__ uint32_t smem_u32(const void* p) {
    uint32_t a;
    asm("{ .reg .u64 t; cvta.to.shared.u64 t, %1; cvt.u32.u64 %0, t; }" : "=r"(a) : "l"(p));
    return a;
}
__device__ __forceinline__ void cp_async16u(uint32_t daddr, const float* src) {
    asm volatile("cp.async.cg.shared.global [%0], [%1], 16;\n" :: "r"(daddr), "l"(src));
}
#define CP_COMMIT() asm volatile("cp.async.commit_group;\n" ::: "memory")

__device__ __forceinline__ uint32_t f2tf32(float f) {
    uint32_t r;
    asm("cvt.rna.tf32.f32 %0, %1;" : "=r"(r) : "f"(f));
    return r;
}
__device__ __forceinline__ uint32_t u2tf32(uint32_t u) {
    return f2tf32(__uint_as_float(u));
}

// ---------------------------------------------------------------------------
__global__ void reset_kernel(float4* out, int n4) {
    int idx = blockIdx.x * blockDim.x + threadIdx.x;
    float4 z = make_float4(0.f, 0.f, 0.f, 0.f);
    for (int i = idx; i < n4; i += gridDim.x * blockDim.x) out[i] = z;
    if (idx < NEXP) g_counts[idx] = 0;
}

// One warp per token: noisy top-2 router.
__global__ void router_kernel(const float* __restrict__ x, const float* __restrict__ noise,
                              const float* __restrict__ Wg, const float* __restrict__ bg,
                              const float* __restrict__ Wn, const float* __restrict__ bn) {
    int gw = (blockIdx.x * blockDim.x + threadIdx.x) >> 5;
    int lane = threadIdx.x & 31;
    if (gw >= T_TOKENS) return;
    const float* xr = x + (size_t)gw * DMODEL;
    float lg[NEXP], ln[NEXP];
#pragma unroll
    for (int e = 0; e < NEXP; e++) { lg[e] = 0.f; ln[e] = 0.f; }
    for (int d = lane; d < DMODEL; d += 32) {
        float xv = xr[d];
#pragma unroll
        for (int e = 0; e < NEXP; e++) {
            lg[e] += xv * Wg[d * NEXP + e];
            ln[e] += xv * Wn[d * NEXP + e];
        }
    }
#pragma unroll
    for (int o = 16; o > 0; o >>= 1) {
#pragma unroll
        for (int e = 0; e < NEXP; e++) {
            lg[e] += __shfl_xor_sync(0xffffffffu, lg[e], o);
            ln[e] += __shfl_xor_sync(0xffffffffu, ln[e], o);
        }
    }
    if (lane == 0) {
        float nv[NEXP];
#pragma unroll
        for (int e = 0; e < NEXP; e++) {
            float nl = ln[e] + bn[e];
            float sp = (nl > 20.f) ? nl : log1pf(expf(nl));
            nv[e] = lg[e] + bg[e] + noise[gw * NEXP + e] * sp;
        }
        int i0 = 0;
#pragma unroll
        for (int e = 1; e < NEXP; e++) if (nv[e] > nv[i0]) i0 = e;
        int i1 = (i0 == 0) ? 1 : 0;
#pragma unroll
        for (int e = 0; e < NEXP; e++) if (e != i0 && nv[e] > nv[i1]) i1 = e;
        float e1 = expf(nv[i1] - nv[i0]);
        float s = 1.f + e1;
        g_topi[gw * 2]     = i0;  g_topg[gw * 2]     = 1.f / s;
        g_topi[gw * 2 + 1] = i1;  g_topg[gw * 2 + 1] = e1 / s;
        atomicAdd(&g_counts[i0], 1);
        atomicAdd(&g_counts[i1], 1);
    }
}

__global__ void offsets_kernel() {
    if (threadIdx.x == 0) {
        int acc = 0;
        for (int e = 0; e < NEXP; e++) {
            g_off[e] = acc; g_cursor[e] = acc; acc += g_counts[e];
        }
        g_off[NEXP] = acc;
    }
}

__global__ void scatter_kernel() {
    int t = blockIdx.x * blockDim.x + threadIdx.x;
    if (t >= T_TOKENS) return;
#pragma unroll
    for (int k = 0; k < TOPK; k++) {
        int e = g_topi[t * 2 + k];
        int pos = atomicAdd(&g_cursor[e], 1);
        g_tok[pos]  = t;
        g_gate[pos] = g_topg[t * 2 + k];
    }
}

// ---------------------------------------------------------------------------
// Grouped GEMM: mma.sync.m16n8k8 tf32, ldmatrix A, conflict-free scalar-LDS B,
// 3-stage cp.async ring.
//   PHASE 0: h = relu(gather(x) @ W1 + b1)   K=1024, N=4096
//   PHASE 1: out += gate * (h @ W2 + b2)     K=4096, N=1024
#define BM 128
#define BN 128
#define BK 32
#define NSTG 3
#define LDB 136                               // floats; k-stride ≡ 8 mod 32 → conflict-free
#define A_BYTES   (BM * 128)                  // 16384 (128B swizzled rows)
#define B_BYTES   (BK * LDB * 4)              // 17408
#define STG_BYTES (A_BYTES + B_BYTES)         // 33792
#define SMEM_BIAS (NSTG * STG_BYTES)
#define SMEM_TOTAL (SMEM_BIAS + BN * 4)       // 101888

__device__ __forceinline__ void mma_tf32(float* c, const uint32_t* a, const uint32_t* b) {
    asm volatile(
        "mma.sync.aligned.m16n8k8.row.col.f32.tf32.tf32.f32 "
        "{%0,%1,%2,%3}, {%4,%5,%6,%7}, {%8,%9}, {%0,%1,%2,%3};"
        : "+f"(c[0]), "+f"(c[1]), "+f"(c[2]), "+f"(c[3])
        : "r"(a[0]), "r"(a[1]), "r"(a[2]), "r"(a[3]), "r"(b[0]), "r"(b[1]));
}
__device__ __forceinline__ void ldsm_x4(uint32_t* r, uint32_t addr) {
    asm volatile("ldmatrix.sync.aligned.m8n8.x4.shared.b16 {%0,%1,%2,%3}, [%4];"
                 : "=r"(r[0]), "=r"(r[1]), "=r"(r[2]), "=r"(r[3]) : "r"(addr));
}

template <int PHASE>
__global__ __launch_bounds__(256, 2)
void moe_gemm_mma(const float* __restrict__ x,
                  const float* __restrict__ W1, const float* __restrict__ b1,
                  const float* __restrict__ W2, const float* __restrict__ b2,
                  float* __restrict__ out) {
    constexpr int K  = PHASE ? DFFN : DMODEL;
    constexpr int NN = PHASE ? DMODEL : DFFN;

    int e  = blockIdx.x >> 6;
    int mt = blockIdx.x & (MT_MAX - 1);
    int off0  = g_off[e];
    int count = g_off[e + 1] - off0;
    if (mt * BM >= count) return;
    int n0 = blockIdx.y * BN;

    extern __shared__ char smem[];
    uint32_t sb = smem_u32(smem);
    float* sBias = (float*)(smem + SMEM_BIAS);

    int tid  = threadIdx.x;
    int wid  = tid >> 5;
    int lane = tid & 31;
    int wm = wid & 3;              // 4 warps along M (32 rows)
    int wn = wid >> 2;             // 2 warps along N (64 cols)

    const float* bias = PHASE ? (b2 + e * DMODEL) : (b1 + e * DFFN);
    if (tid < BN) sBias[tid] = bias[n0 + tid];

    const float* Bsrc = PHASE ? (W2 + (size_t)e * DFFN * DMODEL)
                              : (W1 + (size_t)e * DMODEL * DFFN);

    // ---- per-thread cp.async assignments ----
    // A: 128 rows x 8 chunks(16B), swizzled: off = row*128 + ((chunk^ (row&7))<<4)
    int ac = tid & 7;              // chunk
    const float* aP[4];
    uint32_t aDst[4];
#pragma unroll
    for (int i = 0; i < 4; i++) {
        int idx = tid + i * 256;
        int row = idx >> 3;
        int lr = mt * BM + row;
        if (lr >= count) lr = count - 1;
        int slot = off0 + lr;
        const float* base = PHASE ? (g_h + (size_t)slot * DFFN)
                                  : (x + (size_t)g_tok[slot] * DMODEL);
        aP[i]  = base + ac * 4;
        aDst[i] = (uint32_t)(row * 128 + ((ac ^ (row & 7)) << 4));
    }
    // B: 32 k-rows x 32 chunks(16B of the 128 floats), row stride LDB floats
    int bkr = tid >> 3;            // reuse tid partition: idx>>5 below
    (void)bkr;

    const int nIter = K / BK;

    auto prefetch = [&](int s, int k0) {
        uint32_t ab = sb + s * STG_BYTES;
        uint32_t bb = ab + A_BYTES;
#pragma unroll
        for (int i = 0; i < 4; i++)
            cp_async16u(ab + aDst[i], aP[i] + k0);
#pragma unroll
        for (int i = 0; i < 4; i++) {
            int idx = tid + i * 256;
            int kr = idx >> 5, c = idx & 31;
            cp_async16u(bb + (uint32_t)(kr * LDB * 4 + c * 16),
                        Bsrc + (size_t)(k0 + kr) * NN + n0 + c * 4);
        }
    };

#pragma unroll
    for (int p = 0; p < NSTG; p++) { prefetch(p, p * BK); CP_COMMIT(); }

    float acc[2][8][4];
#pragma unroll
    for (int mi = 0; mi < 2; mi++)
#pragma unroll
        for (int nj = 0; nj < 8; nj++)
#pragma unroll
            for (int r = 0; r < 4; r++) acc[mi][nj][r] = 0.f;

    // ldmatrix per-lane address components (A frag, m16 x k8)
    int lrow = (lane & 7) + (((lane >> 3) & 1) << 3);   // 0..15 within m16 block
    int lchv = lane >> 4;                                // 0/1 -> chunk parity
    int btg  = lane & 3;                                 // B k within k4
    int bgq  = lane >> 2;                                // B n within n8

    for (int i = 0; i < nIter; i++) {
        asm volatile("cp.async.wait_group %0;\n" :: "n"(NSTG - 1) : "memory");
        __syncthreads();
        int s = i % NSTG;
        uint32_t aBase = sb + s * STG_BYTES;
        const float* Bs = (const float*)(smem + s * STG_BYTES + A_BYTES);

#pragma unroll
        for (int ks = 0; ks < 4; ks++) {
            uint32_t ra[2][4];
#pragma unroll
            for (int mi = 0; mi < 2; mi++) {
                int row = wm * 32 + mi * 16 + lrow;
                int chunk = 2 * ks + lchv;
                uint32_t addr = aBase + (uint32_t)(row * 128 + ((chunk ^ (row & 7)) << 4));
                ldsm_x4(ra[mi], addr);
#pragma unroll
                for (int r = 0; r < 4; r++) ra[mi][r] = u2tf32(ra[mi][r]);
            }
            uint32_t rb[8][2];
            const float* bp = Bs + (ks * 8 + btg) * LDB + wn * 64 + bgq;
#pragma unroll
            for (int nj = 0; nj < 8; nj++) {
                rb[nj][0] = f2tf32(bp[nj * 8]);
                rb[nj][1] = f2tf32(bp[nj * 8 + 4 * LDB]);
            }
#pragma unroll
            for (int mi = 0; mi < 2; mi++)
#pragma unroll
                for (int nj = 0; nj < 8; nj++)
                    mma_tf32(acc[mi][nj], ra[mi], rb[nj]);
        }
        __syncthreads();
        if (i + NSTG < nIter) { prefetch(s, (i + NSTG) * BK); CP_COMMIT(); }
    }

    // ---- epilogue straight from registers ----
    int g  = lane >> 2;            // row within 8-group
    int tg = lane & 3;             // col pair selector
#pragma unroll
    for (int mi = 0; mi < 2; mi++) {
#pragma unroll
        for (int half = 0; half < 2; half++) {
            int lr = mt * BM + wm * 32 + mi * 16 + half * 8 + g;
            if (lr >= count) continue;
            int slot = off0 + lr;
            if (PHASE == 0) {
                float* hrow = g_h + (size_t)slot * DFFN + n0;
#pragma unroll
                for (int nj = 0; nj < 8; nj++) {
                    int cl = wn * 64 + nj * 8 + tg * 2;
                    float2 v;
                    v.x = fmaxf(acc[mi][nj][half * 2 + 0] + sBias[cl],     0.f);
                    v.y = fmaxf(acc[mi][nj][half * 2 + 1] + sBias[cl + 1], 0.f);
                    *(float2*)(hrow + cl) = v;
                }
            } else {
                float gate = g_gate[slot];
                float* orow = out + (size_t)g_tok[slot] * DMODEL + n0;
#pragma unroll
                for (int nj = 0; nj < 8; nj++) {
                    int cl = wn * 64 + nj * 8 + tg * 2;
                    float v0 = (acc[mi][nj][half * 2 + 0] + sBias[cl])     * gate;
                    float v1 = (acc[mi][nj][half * 2 + 1] + sBias[cl + 1]) * gate;
                    asm volatile("red.global.add.f32 [%0], %1;" :: "l"(orow + cl),     "f"(v0) : "memory");
                    asm volatile("red.global.add.f32 [%0], %1;" :: "l"(orow + cl + 1), "f"(v1) : "memory");
                }
            }
        }
    }
}

// ---------------------------------------------------------------------------
extern "C" void kernel_launch(void* const* d_in, const int* in_sizes, int n_in,
                              void* d_out, int out_size) {
    const float* x     = (const float*)d_in[0];
    const float* noise = (const float*)d_in[1];
    const float* Wg    = (const float*)d_in[2];
    const float* bg    = (const float*)d_in[3];
    const float* Wn    = (const float*)d_in[4];
    const float* bn    = (const float*)d_in[5];
    const float* W1    = (const float*)d_in[6];
    const float* b1    = (const float*)d_in[7];
    const float* W2    = (const float*)d_in[8];
    const float* b2    = (const float*)d_in[9];
    float* out = (float*)d_out;

    cudaFuncSetAttribute(moe_gemm_mma<0>, cudaFuncAttributeMaxDynamicSharedMemorySize, SMEM_TOTAL);
    cudaFuncSetAttribute(moe_gemm_mma<1>, cudaFuncAttributeMaxDynamicSharedMemorySize, SMEM_TOTAL);

    reset_kernel<<<1024, 256>>>((float4*)out, out_size / 4);                    // 1
    router_kernel<<<(T_TOKENS * 32) / 256, 256>>>(x, noise, Wg, bg, Wn, bn);    // 2
    offsets_kernel<<<1, 32>>>();                                                // 3
    scatter_kernel<<<T_TOKENS / 256, 256>>>();                                  // 4
    moe_gemm_mma<0><<<dim3(NEXP * MT_MAX, DFFN / BN), 256, SMEM_TOTAL>>>(x, W1, b1, W2, b2, out);  // 5
    moe_gemm_mma<1><<<dim3(NEXP * MT_MAX, DMODEL / BN), 256, SMEM_TOTAL>>>(x, W1, b1, W2, b2, out); // 6
}